// round 1
// baseline (speedup 1.0000x reference)
#include <cuda_runtime.h>
#include <math.h>

// Problem constants (fixed shapes from reference: d2 [16, 8192, 256] fp32)
constexpr int B   = 16;
constexpr int L   = 8192;
constexpr int K   = 256;
constexpr float LAMF = 0.95f;
constexpr float OMF  = (float)(1.0 - 0.95);   // 0.05f

// Chunked-scan config
constexpr int C   = 64;          // chunks along time
constexpr int T   = L / C;       // 128 steps per chunk
constexpr int K4  = K / 4;       // 64 float4 lanes per row
constexpr int SEQ = B * K4;      // 1024 independent vec4 sequences

// Scratch for chunk carries / carry-ins: [C][SEQ] float4 = 1 MiB (static, no alloc)
__device__ float4 g_carry[C * SEQ];

__device__ __forceinline__ void ema_step(float4& z, const float4 x) {
    z.x = fmaf(LAMF, z.x, OMF * x.x);
    z.y = fmaf(LAMF, z.y, OMF * x.y);
    z.z = fmaf(LAMF, z.z, OMF * x.z);
    z.w = fmaf(LAMF, z.w, OMF * x.w);
}

// Pass 1: local scan per chunk (zero init), record chunk-final z.
__global__ __launch_bounds__(256) void pft_pass1(const float4* __restrict__ d2) {
    const int tid = blockIdx.x * blockDim.x + threadIdx.x;   // 0 .. C*SEQ-1
    const int bk4 = tid & (SEQ - 1);   // k4 fastest -> coalesced
    const int c   = tid >> 10;         // / SEQ
    const int b   = bk4 >> 6;          // / K4
    const int k4  = bk4 & (K4 - 1);

    const float4* p = d2 + (size_t)(b * L + c * T) * K4 + k4;

    float4 z = make_float4(0.f, 0.f, 0.f, 0.f);
    #pragma unroll 8
    for (int t = 0; t < T; ++t) {
        float4 x = p[(size_t)t * K4];
        ema_step(z, x);
    }
    g_carry[c * SEQ + bk4] = z;        // fully coalesced store
}

// Pass 2: serial scan of carries across chunks for each sequence.
// After this, g_carry[c][s] holds the EXACT carry-in z for chunk c.
__global__ __launch_bounds__(256) void pft_pass2() {
    const int tid = blockIdx.x * blockDim.x + threadIdx.x;   // 0 .. SEQ-1
    if (tid >= SEQ) return;
    const float lamT = (float)pow(0.95, (double)T);          // lambda^T

    float4 run = make_float4(0.f, 0.f, 0.f, 0.f);            // carry-in for chunk 0
    for (int c = 0; c < C; ++c) {
        float4 e = g_carry[c * SEQ + tid];                   // chunk-local final z
        g_carry[c * SEQ + tid] = run;                        // overwrite with carry-in
        run.x = fmaf(lamT, run.x, e.x);
        run.y = fmaf(lamT, run.y, e.y);
        run.z = fmaf(lamT, run.z, e.z);
        run.w = fmaf(lamT, run.w, e.w);
    }
}

// Pass 3: re-run local scan seeded with exact carry-in, write outputs.
__global__ __launch_bounds__(256) void pft_pass3(const float4* __restrict__ d2,
                                                 float4* __restrict__ out) {
    const int tid = blockIdx.x * blockDim.x + threadIdx.x;
    const int bk4 = tid & (SEQ - 1);
    const int c   = tid >> 10;
    const int b   = bk4 >> 6;
    const int k4  = bk4 & (K4 - 1);

    const size_t base = (size_t)(b * L + c * T) * K4 + k4;
    const float4* p = d2  + base;
    float4*       q = out + base;

    float4 z = g_carry[c * SEQ + bk4];
    #pragma unroll 8
    for (int t = 0; t < T; ++t) {
        float4 x = p[(size_t)t * K4];
        ema_step(z, x);
        q[(size_t)t * K4] = z;
    }
}

extern "C" void kernel_launch(void* const* d_in, const int* in_sizes, int n_in,
                              void* d_out, int out_size) {
    (void)in_sizes; (void)n_in; (void)out_size;
    const float4* d2 = (const float4*)d_in[0];
    float4* out = (float4*)d_out;

    pft_pass1<<<(C * SEQ) / 256, 256>>>(d2);
    pft_pass2<<<SEQ / 256, 256>>>();
    pft_pass3<<<(C * SEQ) / 256, 256>>>(d2, out);
}

// round 2
// speedup vs baseline: 1.4652x; 1.4652x over previous
#include <cuda_runtime.h>
#include <math.h>

// Shapes fixed by reference: d2 [16, 8192, 256] fp32
constexpr int B = 16, L = 8192, K = 256;
constexpr float LAM = 0.95f, OM = 0.05f;

constexpr int T   = 128;             // timesteps per tile
constexpr int C   = L / T;           // 64 chunks per (b, k-half) row
constexpr int KS  = 128;             // k-columns per CTA
constexpr int NROW = B * (K / KS);   // 32 independent rows
constexpr int NCTA = NROW * C;       // 2048 CTAs
constexpr int THREADS = KS;          // 1 thread per k-column
constexpr int LOOKBACK = 3;          // lam^(3T) ~ 2.8e-9 -> exact enough
constexpr int TILE_F4 = T * KS / 4;  // 4096 float4 per tile

__device__ float g_agg[NCTA * KS];   // per-CTA chunk-final z (zero-seeded)
__device__ int   g_flag[NCTA];       // publish flags (reset every launch)

__global__ void pft_reset() {
    int i = blockIdx.x * blockDim.x + threadIdx.x;
    if (i < NCTA) g_flag[i] = 0;
}

__global__ __launch_bounds__(THREADS) void pft_scan(const float* __restrict__ d2,
                                                    float* __restrict__ out) {
    extern __shared__ float smem[];        // [T][KS] = 64 KB
    const int bid = blockIdx.x;
    const int c   = bid & (C - 1);         // chunk index; predecessor = bid-1
    const int row = bid >> 6;              // (b, k-half)
    const int tid = threadIdx.x;

    const int b  = row >> 1;
    const int kh = row & 1;
    const size_t base = ((size_t)b * L + (size_t)c * T) * K + (size_t)kh * KS;

    // ---- Phase 1: stage tile into SMEM (fully independent loads, deep MLP)
    const float4* g4 = (const float4*)(d2 + base);   // row stride = K/4 float4
    float4* s4 = (float4*)smem;
    #pragma unroll
    for (int it = 0; it < TILE_F4 / THREADS; ++it) { // 32 loads per thread
        int i4 = tid + it * THREADS;
        int t = i4 >> 5, lane = i4 & 31;             // KS/4 = 32 lanes per row
        s4[i4] = g4[t * (K / 4) + lane];
    }
    __syncthreads();

    // ---- Phase 2: local scan (zero seed) -> aggregate
    float z = 0.f;
    #pragma unroll 16
    for (int t = 0; t < T; ++t)
        z = fmaf(LAM, z, OM * smem[t * KS + tid]);

    // ---- Phase 3: publish aggregate, then release flag
    g_agg[bid * KS + tid] = z;
    __syncthreads();                       // all aggregate stores done (block-visible)
    if (tid == 0) {
        __threadfence();                   // make them gpu-visible before flag
        atomicExch(&g_flag[bid], 1);
    }

    // ---- Phase 4: truncated lookback (depth 3, no prefix chain)
    const int nb = (c < LOOKBACK) ? c : LOOKBACK;
    if (tid == 0) {
        for (int j = 1; j <= nb; ++j)
            while (((volatile int*)g_flag)[bid - j] == 0) __nanosleep(32);
        __threadfence();                   // acquire: aggregates now visible
    }
    __syncthreads();

    float carry = 0.f;
    {
        const float lamT = powf(LAM, (float)T);      // 0.95^128 ~ 1.41e-3
        float f = 1.f;
        for (int j = 1; j <= nb; ++j) {
            carry = fmaf(f, g_agg[(bid - j) * KS + tid], carry);
            f *= lamT;
        }
    }

    // ---- Phase 5: seeded re-scan from SMEM, write output (DRAM write once)
    float* o = out + base;
    float zo = carry;
    #pragma unroll 16
    for (int t = 0; t < T; ++t) {
        zo = fmaf(LAM, zo, OM * smem[t * KS + tid]);
        o[t * K + tid] = zo;               // warp writes 128B contiguous per step
    }
}

extern "C" void kernel_launch(void* const* d_in, const int* in_sizes, int n_in,
                              void* d_out, int out_size) {
    (void)in_sizes; (void)n_in; (void)out_size;
    const float* d2 = (const float*)d_in[0];
    float* out = (float*)d_out;

    static_assert(T * KS * 4 == 65536, "tile is 64KB");
    cudaFuncSetAttribute(pft_scan, cudaFuncAttributeMaxDynamicSharedMemorySize, 65536);

    pft_reset<<<(NCTA + 255) / 256, 256>>>();
    pft_scan<<<NCTA, THREADS, 65536>>>(d2, out);
}

// round 4
// speedup vs baseline: 1.5458x; 1.0550x over previous
#include <cuda_runtime.h>

// Shapes fixed by reference: d2 [16, 8192, 256] fp32
constexpr int B = 16, L = 8192, K = 256;
constexpr float LAM = 0.95f, OM = 0.05f;
constexpr float LAM_TR = 0.19371148f;   // 0.95^32

constexpr int TR   = 32;            // timesteps per CTA (register-resident)
constexpr int C    = L / TR;        // 256 chunks per batch row
constexpr int NCTA = B * C;         // 4096 CTAs
constexpr int LOOKBACK = 12;        // lam^(12*32) = 2.8e-9 -> exact enough

__device__ float g_agg[NCTA * K];   // per-CTA zero-seeded chunk-final z
__device__ int   g_flag[NCTA];

__global__ void pft_reset() {
    int i = blockIdx.x * blockDim.x + threadIdx.x;
    if (i < NCTA) g_flag[i] = 0;
}

__global__ __launch_bounds__(256) void pft_scan(const float* __restrict__ d2,
                                                float* __restrict__ out) {
    const int bid = blockIdx.x;
    const int c   = bid & (C - 1);          // chunk index within row
    const int b   = bid >> 8;               // batch row
    const int tid = threadIdx.x;            // k index (0..255)

    const size_t base = ((size_t)b * L + (size_t)c * TR) * K + tid;

    // ---- Load tile into registers (32 independent coalesced loads)
    float x[TR];
    #pragma unroll
    for (int t = 0; t < TR; ++t)
        x[t] = d2[base + (size_t)t * K];

    // ---- Zero-seeded local scan, in place
    float z = 0.f;
    #pragma unroll
    for (int t = 0; t < TR; ++t) {
        z = fmaf(LAM, z, OM * x[t]);
        x[t] = z;
    }

    // ---- Publish aggregate, release flag
    g_agg[bid * K + tid] = z;
    __threadfence();
    __syncthreads();
    if (tid == 0) atomicExch(&g_flag[bid], 1);

    // ---- Truncated lookback (depth 12, no serial prefix chain)
    const int nb = (c < LOOKBACK) ? c : LOOKBACK;
    if (tid == 0) {
        for (int j = 1; j <= nb; ++j)
            while (((volatile int*)g_flag)[bid - j] == 0) __nanosleep(32);
        __threadfence();
    }
    __syncthreads();

    float carry = 0.f;
    {
        float w = 1.f;                       // lam^((j-1)*TR)
        for (int j = 1; j <= nb; ++j) {
            carry = fmaf(w, g_agg[(bid - j) * K + tid], carry);
            w *= LAM_TR;
        }
    }

    // ---- Fixup: z_exact(t) = z_local(t) + carry * lam^(t+1)
    float cf = carry;
    #pragma unroll
    for (int t = 0; t < TR; ++t) {
        cf *= LAM;
        x[t] += cf;
    }

    // ---- Store (32 coalesced stores)
    #pragma unroll
    for (int t = 0; t < TR; ++t)
        out[base + (size_t)t * K] = x[t];
}

extern "C" void kernel_launch(void* const* d_in, const int* in_sizes, int n_in,
                              void* d_out, int out_size) {
    (void)in_sizes; (void)n_in; (void)out_size;
    const float* d2 = (const float*)d_in[0];
    float* out = (float*)d_out;

    pft_reset<<<(NCTA + 255) / 256, 256>>>();
    pft_scan<<<NCTA, 256>>>(d2, out);
}

// round 5
// speedup vs baseline: 1.7242x; 1.1154x over previous
#include <cuda_runtime.h>

// Shapes fixed by reference: d2 [16, 8192, 256] fp32
constexpr int B = 16, L = 8192, K = 256, K4 = 64;
constexpr float LAM = 0.95f, OM = 0.05f;

constexpr int TR  = 16;             // timesteps per sub-chunk (register tile)
constexpr int GRP = 4;              // sub-chunks per CTA
constexpr int TRC = TR * GRP;       // 64 timesteps per CTA
constexpr int CPR = L / TRC;        // 128 CTAs per batch row
constexpr int NCTA = B * CPR;       // 2048
constexpr int D   = 5;              // CTA lookback depth: (0.95^64)^5 ~ 7e-8

__device__ float4 g_aggA[NCTA * K4];  // per-CTA zero-seeded 64-step aggregate
__device__ int    g_flag[NCTA];

__device__ __forceinline__ float4 f4fma(float a, float4 x, float4 y) {
    return make_float4(fmaf(a, x.x, y.x), fmaf(a, x.y, y.y),
                       fmaf(a, x.z, y.z), fmaf(a, x.w, y.w));
}
__device__ __forceinline__ float4 f4scale(float a, float4 x) {
    return make_float4(a * x.x, a * x.y, a * x.z, a * x.w);
}

__global__ void pft_reset() {
    int i = blockIdx.x * blockDim.x + threadIdx.x;
    if (i < NCTA) g_flag[i] = 0;
}

__global__ __launch_bounds__(256, 2) void pft_scan(const float4* __restrict__ d2,
                                                   float4* __restrict__ out) {
    __shared__ float4 s_agg[GRP][K4];   // sub-chunk aggregates
    __shared__ float4 s_zin[K4];        // exact z at CTA entry

    const int bid  = blockIdx.x;
    const int ct   = bid & (CPR - 1);   // CTA index within row
    const int b    = bid >> 7;          // batch row
    const int tid  = threadIdx.x;
    const int lane = tid & (K4 - 1);    // k4 lane
    const int s    = tid >> 6;          // sub-chunk 0..3

    // lam^(16*i): 1, lam^16, lam^32, lam^48
    const float PW[4] = {1.f, 0.44012667f, 0.19371148f, 0.08525553f};

    const size_t base = ((size_t)b * L + (size_t)ct * TRC + (size_t)s * TR) * K4 + lane;

    // ---- Load 16 float4 (independent, coalesced 512B per warp access)
    float4 x[TR];
    #pragma unroll
    for (int t = 0; t < TR; ++t)
        x[t] = d2[base + (size_t)t * K4];

    // ---- Zero-seeded local scan in registers
    float4 z = make_float4(0.f, 0.f, 0.f, 0.f);
    #pragma unroll
    for (int t = 0; t < TR; ++t) {
        z.x = fmaf(LAM, z.x, OM * x[t].x);
        z.y = fmaf(LAM, z.y, OM * x[t].y);
        z.z = fmaf(LAM, z.z, OM * x[t].z);
        z.w = fmaf(LAM, z.w, OM * x[t].w);
        x[t] = z;
    }
    s_agg[s][lane] = z;
    __syncthreads();

    // ---- Combine sub-aggregates into CTA aggregate, publish
    if (tid < K4) {
        float4 A = s_agg[3][tid];
        A = f4fma(PW[1], s_agg[2][tid], A);
        A = f4fma(PW[2], s_agg[1][tid], A);
        A = f4fma(PW[3], s_agg[0][tid], A);
        g_aggA[bid * K4 + tid] = A;
    }
    __syncthreads();
    if (tid == 0) { __threadfence(); atomicExch(&g_flag[bid], 1); }

    // ---- Inter-CTA truncated lookback (depth 5, ratio lam^64)
    const int nb = (ct < D) ? ct : D;
    if (tid < K4) {
        for (int j = 1; j <= nb; ++j)
            while (((volatile int*)g_flag)[bid - j] == 0) __nanosleep(20);
        __threadfence();
        float4 zin = make_float4(0.f, 0.f, 0.f, 0.f);
        float w = 1.f;                       // (lam^64)^(j-1)
        for (int j = 1; j <= nb; ++j) {
            zin = f4fma(w, g_aggA[(bid - j) * K4 + tid], zin);
            w *= 0.03752414f;                // lam^64
        }
        s_zin[tid] = zin;
    }
    __syncthreads();

    // ---- Carry at this sub-chunk's entry
    float4 carry = f4scale(PW[s], s_zin[lane]);
    for (int i = 0; i < s; ++i)
        carry = f4fma(PW[s - 1 - i], s_agg[i][lane], carry);

    // ---- Fixup z_exact(t) = z_local(t) + carry*lam^(t+1), store
    #pragma unroll
    for (int t = 0; t < TR; ++t) {
        carry = f4scale(LAM, carry);
        x[t].x += carry.x;
        x[t].y += carry.y;
        x[t].z += carry.z;
        x[t].w += carry.w;
        out[base + (size_t)t * K4] = x[t];
    }
}

extern "C" void kernel_launch(void* const* d_in, const int* in_sizes, int n_in,
                              void* d_out, int out_size) {
    (void)in_sizes; (void)n_in; (void)out_size;
    const float4* d2 = (const float4*)d_in[0];
    float4* out = (float4*)d_out;

    pft_reset<<<(NCTA + 255) / 256, 256>>>();
    pft_scan<<<NCTA, 256>>>(d2, out);
}